// round 14
// baseline (speedup 1.0000x reference)
#include <cuda_runtime.h>
#include <cuda_bf16.h>
#include <cstdint>

// ---------------------------------------------------------------------------
// GASP_EGNN coordinate update on GB300 (sm_103a) — round 14
// Layer1: FP8 e4m3 mma.sync m16n8k32 (halves weight+input smem bytes).
// Layer2: bf16 m16n8k16 (register A-frag handoff, unchanged from R13).
// Coalesced cp.async double-buffer pipeline, 16 warps, packed bf16x2 SiLU.
// ---------------------------------------------------------------------------

#define HID   64
#define EIN   8
#define EPW   16
#define XSTRIDE 176                   // fp8 row: 160B data + 16B pad (11*16)
#define XTILE   (EPW * XSTRIDE)       // 2816 B per buffer
#define NWARPS  16
#define NTHREADS (NWARPS * 32)
#define NT1   5                       // layer1 k-tiles (K=160, fp8 k32)
#define NT2   5                       // layer2 k-tiles (K=80, bf16 k16)
#define NMAX  50048
#define EMAX  1600000

typedef uint32_t u32;
typedef unsigned long long ull;

__device__ __align__(16) uint8_t g_h8[NMAX * HID];      // e4m3, 64B per node
__device__ __align__(16) uint8_t g_ea8[EMAX * EIN];     // e4m3, 8B per edge

__device__ __forceinline__ u32 smem_u32(const void* p) {
    u32 a;
    asm("{ .reg .u64 t; cvta.to.shared.u64 t, %1; cvt.u32.u64 %0, t; }"
        : "=r"(a) : "l"(p));
    return a;
}
__device__ __forceinline__ u32 cvt2(float a, float b) {
    __nv_bfloat162 t = __floats2bfloat162_rn(a, b);
    return *(u32*)&t;
}
// pack two f32 -> e4m3x2 (byte0 = lo)
__device__ __forceinline__ unsigned short e4m3x2(float lo, float hi) {
    unsigned short r;
    asm("cvt.rn.satfinite.e4m3x2.f32 %0, %1, %2;" : "=h"(r) : "f"(hi), "f"(lo));
    return r;
}
__device__ __forceinline__ u32 pack4_e4m3(float a, float b, float c, float d) {
    return (u32)e4m3x2(a, b) | ((u32)e4m3x2(c, d) << 16);
}
// packed SiLU on bf16x2: silu(x) = h + h*tanh(h), h = 0.5x
__device__ __forceinline__ u32 silu_b2(u32 x) {
    u32 h, t, r;
    asm("mul.rn.bf16x2 %0, %1, %2;" : "=r"(h) : "r"(x), "r"(0x3F003F00u));
    asm("tanh.approx.bf16x2 %0, %1;" : "=r"(t) : "r"(h));
    asm("fma.rn.bf16x2 %0, %1, %2, %1;" : "=r"(r) : "r"(h), "r"(t));
    return r;
}
__device__ __forceinline__ u32 hfma2b(u32 a, u32 b, u32 c) {
    u32 d;
    asm("fma.rn.bf16x2 %0, %1, %2, %3;" : "=r"(d) : "r"(a), "r"(b), "r"(c));
    return d;
}
__device__ __forceinline__ float unpack_sum_b2(u32 p) {
    float lo = __uint_as_float(p << 16);
    float hi = __uint_as_float(p & 0xFFFF0000u);
    return lo + hi;
}
__device__ __forceinline__ void ldsm4(u32& r0, u32& r1, u32& r2, u32& r3, u32 addr) {
    asm volatile("ldmatrix.sync.aligned.m8n8.x4.shared.b16 {%0,%1,%2,%3}, [%4];"
                 : "=r"(r0), "=r"(r1), "=r"(r2), "=r"(r3) : "r"(addr));
}
// bf16 m16n8k16
__device__ __forceinline__ void mma16816(float* d, u32 a0, u32 a1, u32 a2, u32 a3,
                                         u32 b0, u32 b1) {
    asm volatile("mma.sync.aligned.m16n8k16.row.col.f32.bf16.bf16.f32 "
                 "{%0,%1,%2,%3}, {%4,%5,%6,%7}, {%8,%9}, {%0,%1,%2,%3};"
                 : "+f"(d[0]), "+f"(d[1]), "+f"(d[2]), "+f"(d[3])
                 : "r"(a0), "r"(a1), "r"(a2), "r"(a3), "r"(b0), "r"(b1));
}
// fp8 e4m3 m16n8k32
__device__ __forceinline__ void mma16832f8(float* d, u32 a0, u32 a1, u32 a2, u32 a3,
                                           u32 b0, u32 b1) {
    asm volatile("mma.sync.aligned.m16n8k32.row.col.f32.e4m3.e4m3.f32 "
                 "{%0,%1,%2,%3}, {%4,%5,%6,%7}, {%8,%9}, {%0,%1,%2,%3};"
                 : "+f"(d[0]), "+f"(d[1]), "+f"(d[2]), "+f"(d[3])
                 : "r"(a0), "r"(a1), "r"(a2), "r"(a3), "r"(b0), "r"(b1));
}
__device__ __forceinline__ void cpa16(u32 dst, const void* src) {
    asm volatile("cp.async.ca.shared.global [%0], [%1], 16;"
                 :: "r"(dst), "l"(src) : "memory");
}
__device__ __forceinline__ void cpa8(u32 dst, const void* src) {
    asm volatile("cp.async.ca.shared.global [%0], [%1], 8;"
                 :: "r"(dst), "l"(src) : "memory");
}
#define CPA_COMMIT() asm volatile("cp.async.commit_group;" ::: "memory")
#define CPA_WAIT1()  asm volatile("cp.async.wait_group 1;" ::: "memory")

// fused prep: out init + h->e4m3 + ea->e4m3 (one launch)
__global__ void prep_kernel(const float* __restrict__ h, const float* __restrict__ ea,
                            const float* __restrict__ coord, float* __restrict__ out,
                            int h4, int e4, int nout) {
    int i = blockIdx.x * blockDim.x + threadIdx.x;
    if (i < h4) {
        float4 v = ((const float4*)h)[i];
        ((u32*)g_h8)[i] = pack4_e4m3(v.x, v.y, v.z, v.w);
    }
    if (i < e4) {
        float4 v = ((const float4*)ea)[i];
        ((u32*)g_ea8)[i] = pack4_e4m3(v.x, v.y, v.z, v.w);
    }
    if (i < nout) out[i] = coord[i];
}

// smem: sB1f 5*8*32*8=10240 | sB2f 10240 | sW3 256 | X dbl-buffers 16*2*2816
#define SB1_OFF  0
#define SB2_OFF  10240
#define SW3_OFF  20480
#define SX_OFF   (SW3_OFF + 256)
#define SMEM_BYTES (SX_OFF + NWARPS * 2 * XTILE)   // 110,848 B

__global__ __launch_bounds__(NTHREADS, 1)
void egnn_mma_kernel(
    const float* __restrict__ coord,
    const int*   __restrict__ ei,
    const float* __restrict__ W1, const float* __restrict__ b1,
    const float* __restrict__ W2, const float* __restrict__ b2,
    const float* __restrict__ W3, float* __restrict__ out, int E)
{
    extern __shared__ char sm[];
    uint2* sB1f = (uint2*)(sm + SB1_OFF);
    uint2* sB2f = (uint2*)(sm + SB2_OFF);
    float* sW3  = (float*)(sm + SW3_OFF);

    const int tid  = threadIdx.x;
    const int lane = tid & 31;
    const int wid  = tid >> 5;
    char* sXw = sm + SX_OFF + wid * (2 * XTILE);

    // ---- B1 fragments, fp8 m16n8k32 (K=160: k<136=W1, k==136=b1, rest 0) --
    for (int idx = tid; idx < NT1 * 8 * 32; idx += NTHREADS) {
        int t = idx >> 8, j = (idx >> 5) & 7, l = idx & 31;
        int n  = j * 8 + (l >> 2);
        int kb = t * 32 + (l & 3) * 4;
        float v[8];
        #pragma unroll
        for (int q = 0; q < 8; q++) {
            int k = kb + (q >> 2) * 16 + (q & 3);
            v[q] = (k < 136) ? W1[k * HID + n] : ((k == 136) ? b1[n] : 0.0f);
        }
        sB1f[idx] = make_uint2(pack4_e4m3(v[0], v[1], v[2], v[3]),
                               pack4_e4m3(v[4], v[5], v[6], v[7]));
    }
    // ---- B2 fragments, bf16 m16n8k16 (K=80: row 64=b2, rest 0) -------------
    for (int idx = tid; idx < NT2 * 8 * 32; idx += NTHREADS) {
        int t = idx >> 8, j = (idx >> 5) & 7, l = idx & 31;
        int n  = j * 8 + (l >> 2);
        int k0 = t * 16 + (l & 3) * 2;
        float v0 = (k0     < 64) ? W2[k0 * HID + n]       : ((k0     == 64) ? b2[n] : 0.0f);
        float v1 = (k0 + 1 < 64) ? W2[(k0 + 1) * HID + n] : ((k0 + 1 == 64) ? b2[n] : 0.0f);
        int k1 = k0 + 8;
        float v2 = (k1     < 64) ? W2[k1 * HID + n]       : ((k1     == 64) ? b2[n] : 0.0f);
        float v3 = (k1 + 1 < 64) ? W2[(k1 + 1) * HID + n] : ((k1 + 1 == 64) ? b2[n] : 0.0f);
        sB2f[idx] = make_uint2(cvt2(v0, v1), cvt2(v2, v3));
    }
    if (tid < HID) sW3[tid] = W3[tid];

    // ---- X static bytes 136..159: bias e4m3(1.0)=0x38 @136, zeros after ----
    if (lane < 16) {
        #pragma unroll
        for (int bs = 0; bs < 2; bs++) {
            char* row = sXw + bs * XTILE + lane * XSTRIDE;
            *(u32*)(row + 136) = 0x38u;
            *(u32*)(row + 140) = 0u;
            *(ull*)(row + 144) = 0ULL;
            *(ull*)(row + 152) = 0ULL;
        }
    }
    __syncthreads();

    const unsigned FULL = 0xffffffffu;
    const int nwarps  = gridDim.x * NWARPS;
    const int gwid    = blockIdx.x * NWARPS + wid;
    const int ngroups = E / EPW;

    const u32 xbase = smem_u32(sXw);
    const u32 lm_off = (u32)(lane & 15) * XSTRIDE + ((lane & 16) ? 16u : 0u);
    const int l4 = lane & 3;
    const u32 bias_a = (l4 == 0) ? cvt2(1.0f, 0.0f) : 0u;

    u32 w3p[8];
    #pragma unroll
    for (int j = 0; j < 8; j++)
        w3p[j] = cvt2(sW3[j * 8 + l4 * 2], sW3[j * 8 + l4 * 2 + 1]);

    const int rlane = lane >> 2;   // 0..7: row-within-8 for copy step
    const int chunk = lane & 3;    // 16B chunk within a 64B fp8 row

    // ---- prologue: stage tile gwid into buffer 0 ----
    int g = gwid;
    int t_cur = 0;
    if (g < ngroups) {
        if (lane < 16) t_cur = ei[g * EPW + lane];
        else           t_cur = ei[E + g * EPW + lane - 16];
        #pragma unroll
        for (int it = 0; it < 4; it++) {
            int rid  = it * 8 + rlane;                    // 0..31
            int node = __shfl_sync(FULL, t_cur, rid);
            u32 dst = xbase + (u32)(rid & 15) * XSTRIDE + (u32)(rid >> 4) * 64
                      + (u32)chunk * 16;
            cpa16(dst, g_h8 + (size_t)node * 64 + chunk * 16);
        }
        if (lane < 16)
            cpa8(xbase + (u32)lane * XSTRIDE + 128,
                 g_ea8 + (size_t)(g * EPW + lane) * 8);
    }
    CPA_COMMIT();

    int bufsel = 0;
    while (g < ngroups) {
        const int gn = g + nwarps;
        int t_nxt = 0;

        // ---- stage next tile into the other buffer (overlaps this tile) ----
        if (gn < ngroups) {
            if (lane < 16) t_nxt = ei[gn * EPW + lane];
            else           t_nxt = ei[E + gn * EPW + lane - 16];
            const u32 xb = xbase + (u32)(bufsel ^ 1) * XTILE;
            #pragma unroll
            for (int it = 0; it < 4; it++) {
                int rid  = it * 8 + rlane;
                int node = __shfl_sync(FULL, t_nxt, rid);
                u32 dst = xb + (u32)(rid & 15) * XSTRIDE + (u32)(rid >> 4) * 64
                          + (u32)chunk * 16;
                cpa16(dst, g_h8 + (size_t)node * 64 + chunk * 16);
            }
            if (lane < 16)
                cpa8(xb + (u32)lane * XSTRIDE + 128,
                     g_ea8 + (size_t)(gn * EPW + lane) * 8);
        }
        CPA_COMMIT();
        CPA_WAIT1();
        __syncwarp();

        const u32 lm_base = xbase + (u32)bufsel * XTILE + lm_off;

        // ============ layer 1 (fp8): 5 k32-tiles x 8 n-tiles ===============
        float dacc[8][4];
        #pragma unroll
        for (int j = 0; j < 8; j++)
            #pragma unroll
            for (int q = 0; q < 4; q++) dacc[j][q] = 0.0f;

        #pragma unroll
        for (int tt = 0; tt < NT1; tt++) {
            u32 a0, a1, a2, a3;
            ldsm4(a0, a1, a2, a3, lm_base + tt * 32);
            #pragma unroll
            for (int j = 0; j < 8; j++) {
                uint2 b = sB1f[(tt * 8 + j) * 32 + lane];
                mma16832f8(dacc[j], a0, a1, a2, a3, b.x, b.y);
            }
        }

        // ===== pack -> bf16x2, packed SiLU -> layer2 A-frags ===============
        u32 a2f[NT2][4];
        #pragma unroll
        for (int j = 0; j < 8; j++) {
            int t2 = j >> 1, hf = (j & 1) * 2;
            a2f[t2][hf + 0] = silu_b2(cvt2(dacc[j][0], dacc[j][1]));
            a2f[t2][hf + 1] = silu_b2(cvt2(dacc[j][2], dacc[j][3]));
        }
        a2f[4][0] = bias_a; a2f[4][1] = bias_a; a2f[4][2] = 0; a2f[4][3] = 0;

        // ============ layer 2 (bf16): 5 k16-tiles x 8 n-tiles ==============
        float eacc[8][4];
        #pragma unroll
        for (int j = 0; j < 8; j++)
            #pragma unroll
            for (int q = 0; q < 4; q++) eacc[j][q] = 0.0f;

        #pragma unroll
        for (int tt = 0; tt < NT2; tt++) {
            #pragma unroll
            for (int j = 0; j < 8; j++) {
                uint2 b = sB2f[(tt * 8 + j) * 32 + lane];
                mma16816(eacc[j], a2f[tt][0], a2f[tt][1], a2f[tt][2], a2f[tt][3],
                         b.x, b.y);
            }
        }

        // ===== packed SiLU(D2) . W3 (bf16x2 dot), quad reduce ==============
        u32 acc_lo = 0, acc_hi = 0;
        #pragma unroll
        for (int j = 0; j < 8; j++) {
            u32 p0 = silu_b2(cvt2(eacc[j][0], eacc[j][1]));
            u32 p1 = silu_b2(cvt2(eacc[j][2], eacc[j][3]));
            acc_lo = hfma2b(p0, w3p[j], acc_lo);
            acc_hi = hfma2b(p1, w3p[j], acc_hi);
        }
        float s_lo = unpack_sum_b2(acc_lo);
        float s_hi = unpack_sum_b2(acc_hi);
        s_lo += __shfl_xor_sync(FULL, s_lo, 1);
        s_lo += __shfl_xor_sync(FULL, s_lo, 2);
        s_hi += __shfl_xor_sync(FULL, s_hi, 1);
        s_hi += __shfl_xor_sync(FULL, s_hi, 2);

        // ===== epilogue: lane e (0..15) owns edge e ========================
        const int src4 = (lane & 7) * 4;
        float slo_b = __shfl_sync(FULL, s_lo, src4);
        float shi_b = __shfl_sync(FULL, s_hi, src4);
        const float sc = (lane < 8) ? slo_b : shi_b;

        const int rn = __shfl_sync(FULL, t_cur, lane & 15);
        const int cn = __shfl_sync(FULL, t_cur, 16 + (lane & 15));

        if (lane < 16) {
            const float dx = coord[rn * 3 + 0] - coord[cn * 3 + 0];
            const float dy = coord[rn * 3 + 1] - coord[cn * 3 + 1];
            const float dz = coord[rn * 3 + 2] - coord[cn * 3 + 2];
            const float nrm = sqrtf(dx * dx + dy * dy + dz * dz + 1e-8f);
            const float f = sc / ((nrm + 1.0f) * 100.0f);
            atomicAdd(&out[rn * 3 + 0], dx * f);
            atomicAdd(&out[rn * 3 + 1], dy * f);
            atomicAdd(&out[rn * 3 + 2], dz * f);
        }

        t_cur = t_nxt;
        g = gn;
        bufsel ^= 1;
        __syncwarp();
    }
}

extern "C" void kernel_launch(void* const* d_in, const int* in_sizes, int n_in,
                              void* d_out, int out_size)
{
    const float* h     = (const float*)d_in[0];
    const float* coord = (const float*)d_in[1];
    const int*   ei    = (const int*)  d_in[2];
    const float* ea    = (const float*)d_in[3];
    const float* W1    = (const float*)d_in[4];
    const float* b1    = (const float*)d_in[5];
    const float* W2    = (const float*)d_in[6];
    const float* b2    = (const float*)d_in[7];
    const float* W3    = (const float*)d_in[8];
    float* out = (float*)d_out;

    const int E  = in_sizes[3] / EIN;     // 1,600,000
    const int h4 = in_sizes[0] / 4;
    const int e4 = in_sizes[3] / 4;
    const int nmax = (e4 > h4) ? e4 : h4;

    prep_kernel<<<(nmax + 255) / 256, 256>>>(h, ea, coord, out, h4, e4, out_size);

    cudaFuncSetAttribute(egnn_mma_kernel,
                         cudaFuncAttributeMaxDynamicSharedMemorySize, SMEM_BYTES);
    egnn_mma_kernel<<<148, NTHREADS, SMEM_BYTES>>>(coord, ei,
                                                   W1, b1, W2, b2, W3, out, E);
}

// round 15
// speedup vs baseline: 1.1136x; 1.1136x over previous
#include <cuda_runtime.h>
#include <cuda_bf16.h>
#include <cstdint>

// ---------------------------------------------------------------------------
// GASP_EGNN coordinate update on GB300 (sm_103a) — round 15
// = R13 (mma.sync bf16, 16 edges/warp, coalesced cp.async double-buffer,
//   packed bf16x2 SiLU) with ea streamed as raw fp32 via prefetched LDG and
//   converted in-kernel (g_ea precompute removed; prep = h cvt + out init).
// ---------------------------------------------------------------------------

#define HID   64
#define EIN   8
#define EPW   16
#define XSTRIDE 304
#define XTILE   (EPW * XSTRIDE)       // 4864 B per buffer
#define NWARPS  16
#define NTHREADS (NWARPS * 32)
#define NT1   9
#define NT2   5
#define NMAX  50048

typedef uint32_t u32;
typedef unsigned long long ull;

__device__ __align__(16) __nv_bfloat16 g_h[NMAX * HID];

__device__ __forceinline__ u32 smem_u32(const void* p) {
    u32 a;
    asm("{ .reg .u64 t; cvta.to.shared.u64 t, %1; cvt.u32.u64 %0, t; }"
        : "=r"(a) : "l"(p));
    return a;
}
__device__ __forceinline__ u32 cvt2(float a, float b) {
    __nv_bfloat162 t = __floats2bfloat162_rn(a, b);
    return *(u32*)&t;
}
// packed SiLU on bf16x2: silu(x) = h + h*tanh(h), h = 0.5x
__device__ __forceinline__ u32 silu_b2(u32 x) {
    u32 h, t, r;
    asm("mul.rn.bf16x2 %0, %1, %2;" : "=r"(h) : "r"(x), "r"(0x3F003F00u));
    asm("tanh.approx.bf16x2 %0, %1;" : "=r"(t) : "r"(h));
    asm("fma.rn.bf16x2 %0, %1, %2, %1;" : "=r"(r) : "r"(h), "r"(t));
    return r;
}
__device__ __forceinline__ u32 hfma2b(u32 a, u32 b, u32 c) {
    u32 d;
    asm("fma.rn.bf16x2 %0, %1, %2, %3;" : "=r"(d) : "r"(a), "r"(b), "r"(c));
    return d;
}
__device__ __forceinline__ float unpack_sum_b2(u32 p) {
    float lo = __uint_as_float(p << 16);
    float hi = __uint_as_float(p & 0xFFFF0000u);
    return lo + hi;
}
__device__ __forceinline__ void ldsm4(u32& r0, u32& r1, u32& r2, u32& r3, u32 addr) {
    asm volatile("ldmatrix.sync.aligned.m8n8.x4.shared.b16 {%0,%1,%2,%3}, [%4];"
                 : "=r"(r0), "=r"(r1), "=r"(r2), "=r"(r3) : "r"(addr));
}
__device__ __forceinline__ void mma16816(float* d, u32 a0, u32 a1, u32 a2, u32 a3,
                                         u32 b0, u32 b1) {
    asm volatile("mma.sync.aligned.m16n8k16.row.col.f32.bf16.bf16.f32 "
                 "{%0,%1,%2,%3}, {%4,%5,%6,%7}, {%8,%9}, {%0,%1,%2,%3};"
                 : "+f"(d[0]), "+f"(d[1]), "+f"(d[2]), "+f"(d[3])
                 : "r"(a0), "r"(a1), "r"(a2), "r"(a3), "r"(b0), "r"(b1));
}
__device__ __forceinline__ void cpa16(u32 dst, const void* src) {
    asm volatile("cp.async.cg.shared.global [%0], [%1], 16;"
                 :: "r"(dst), "l"(src) : "memory");
}
#define CPA_COMMIT() asm volatile("cp.async.commit_group;" ::: "memory")
#define CPA_WAIT1()  asm volatile("cp.async.wait_group 1;" ::: "memory")

// prep: out init + h->bf16 (ea now streamed raw by the main kernel)
__global__ void prep_kernel(const float* __restrict__ h,
                            const float* __restrict__ coord, float* __restrict__ out,
                            int h4, int nout) {
    int i = blockIdx.x * blockDim.x + threadIdx.x;
    if (i < h4) {
        float4 v = ((const float4*)h)[i];
        ((uint2*)g_h)[i] = make_uint2(cvt2(v.x, v.y), cvt2(v.z, v.w));
    }
    if (i < nout) out[i] = coord[i];
}

// smem bytes: sB1f 18432 | sB2f 10240 | sW3 256 | X double-buffers 16*2*4864
#define SB1_OFF  0
#define SB2_OFF  18432
#define SW3_OFF  (18432 + 10240)
#define SX_OFF   (SW3_OFF + 256)
#define SMEM_BYTES (SX_OFF + NWARPS * 2 * XTILE)   // 184,576 B

__global__ __launch_bounds__(NTHREADS, 1)
void egnn_mma_kernel(
    const float* __restrict__ coord,
    const int*   __restrict__ ei,
    const float* __restrict__ ea,
    const float* __restrict__ W1, const float* __restrict__ b1,
    const float* __restrict__ W2, const float* __restrict__ b2,
    const float* __restrict__ W3, float* __restrict__ out, int E)
{
    extern __shared__ char sm[];
    uint2* sB1f = (uint2*)(sm + SB1_OFF);
    uint2* sB2f = (uint2*)(sm + SB2_OFF);
    float* sW3  = (float*)(sm + SW3_OFF);

    const int tid  = threadIdx.x;
    const int lane = tid & 31;
    const int wid  = tid >> 5;
    char* sXw = sm + SX_OFF + wid * (2 * XTILE);

    // ---- precompute B fragments for W1 (K=144: row 136=b1, rest 0) ---------
    for (int idx = tid; idx < NT1 * 8 * 32; idx += NTHREADS) {
        int t = idx >> 8, j = (idx >> 5) & 7, l = idx & 31;
        int n  = j * 8 + (l >> 2);
        int k0 = t * 16 + (l & 3) * 2;
        float v0 = (k0     < 136) ? W1[k0 * HID + n]       : ((k0     == 136) ? b1[n] : 0.0f);
        float v1 = (k0 + 1 < 136) ? W1[(k0 + 1) * HID + n] : ((k0 + 1 == 136) ? b1[n] : 0.0f);
        int k1 = k0 + 8;
        float v2 = (k1     < 136) ? W1[k1 * HID + n]       : ((k1     == 136) ? b1[n] : 0.0f);
        float v3 = (k1 + 1 < 136) ? W1[(k1 + 1) * HID + n] : ((k1 + 1 == 136) ? b1[n] : 0.0f);
        sB1f[idx] = make_uint2(cvt2(v0, v1), cvt2(v2, v3));
    }
    // ---- precompute B fragments for W2 (K=80: row 64=b2, rest 0) -----------
    for (int idx = tid; idx < NT2 * 8 * 32; idx += NTHREADS) {
        int t = idx >> 8, j = (idx >> 5) & 7, l = idx & 31;
        int n  = j * 8 + (l >> 2);
        int k0 = t * 16 + (l & 3) * 2;
        float v0 = (k0     < 64) ? W2[k0 * HID + n]       : ((k0     == 64) ? b2[n] : 0.0f);
        float v1 = (k0 + 1 < 64) ? W2[(k0 + 1) * HID + n] : ((k0 + 1 == 64) ? b2[n] : 0.0f);
        int k1 = k0 + 8;
        float v2 = (k1     < 64) ? W2[k1 * HID + n]       : ((k1     == 64) ? b2[n] : 0.0f);
        float v3 = (k1 + 1 < 64) ? W2[(k1 + 1) * HID + n] : ((k1 + 1 == 64) ? b2[n] : 0.0f);
        sB2f[idx] = make_uint2(cvt2(v0, v1), cvt2(v2, v3));
    }
    if (tid < HID) sW3[tid] = W3[tid];

    // ---- X pad bytes 272..287 (bias=1 @272, zeros) in BOTH buffers ---------
    if (lane < 16) {
        #pragma unroll
        for (int bs = 0; bs < 2; bs++) {
            *(ull*)(sXw + bs * XTILE + lane * XSTRIDE + 272) = 0x3F80ULL;
            *(ull*)(sXw + bs * XTILE + lane * XSTRIDE + 280) = 0ULL;
        }
    }
    __syncthreads();

    const unsigned FULL = 0xffffffffu;
    const int nwarps  = gridDim.x * NWARPS;
    const int gwid    = blockIdx.x * NWARPS + wid;
    const int ngroups = E / EPW;

    const u32 xbase = smem_u32(sXw);
    const u32 lm_off = (u32)(lane & 15) * XSTRIDE + ((lane & 16) ? 16u : 0u);
    const int l4 = lane & 3;
    const u32 bias_a = (l4 == 0) ? cvt2(1.0f, 0.0f) : 0u;

    // packed W3 pairs for this lane's columns (c = j*8 + l4*2)
    u32 w3p[8];
    #pragma unroll
    for (int j = 0; j < 8; j++)
        w3p[j] = cvt2(sW3[j * 8 + l4 * 2], sW3[j * 8 + l4 * 2 + 1]);

    const int qq4 = lane >> 3;     // row within a 4-row copy step
    const int b16 = lane & 7;      // 16B chunk within a 128B row

    // ---- prologue: stage tile gwid into buffer 0; LDG raw ea for it --------
    int g = gwid;
    int t_cur = 0;
    float4 eaA = make_float4(0, 0, 0, 0), eaB = make_float4(0, 0, 0, 0);
    if (g < ngroups) {
        if (lane < 16) t_cur = ei[g * EPW + lane];
        else           t_cur = ei[E + g * EPW + lane - 16];
        #pragma unroll
        for (int it = 0; it < 8; it++) {
            int rid  = it * 4 + qq4;                      // 0..31
            int node = __shfl_sync(FULL, t_cur, rid);
            int e = rid & 15, s = rid >> 4;
            cpa16(xbase + e * XSTRIDE + s * 128 + b16 * 16,
                  (const char*)g_h + (size_t)node * 128 + b16 * 16);
        }
        if (lane < 16) {
            const float4* ep = (const float4*)(ea + (size_t)(g * EPW + lane) * EIN);
            eaA = ep[0]; eaB = ep[1];
        }
    }
    CPA_COMMIT();

    int bufsel = 0;
    while (g < ngroups) {
        const int gn = g + nwarps;
        int t_nxt = 0;
        float4 eaAn = make_float4(0, 0, 0, 0), eaBn = make_float4(0, 0, 0, 0);

        // ---- stage next tile into the other buffer (overlaps this tile) ----
        if (gn < ngroups) {
            if (lane < 16) t_nxt = ei[gn * EPW + lane];
            else           t_nxt = ei[E + gn * EPW + lane - 16];
            const u32 xb = xbase + (u32)(bufsel ^ 1) * XTILE;
            #pragma unroll
            for (int it = 0; it < 8; it++) {
                int rid  = it * 4 + qq4;
                int node = __shfl_sync(FULL, t_nxt, rid);
                int e = rid & 15, s = rid >> 4;
                cpa16(xb + e * XSTRIDE + s * 128 + b16 * 16,
                      (const char*)g_h + (size_t)node * 128 + b16 * 16);
            }
            if (lane < 16) {
                const float4* ep = (const float4*)(ea + (size_t)(gn * EPW + lane) * EIN);
                eaAn = ep[0]; eaBn = ep[1];      // latency hidden a full tile ahead
            }
        }
        CPA_COMMIT();
        CPA_WAIT1();                          // current tile's h copies done
        __syncwarp();

        // ---- convert this tile's raw fp32 ea -> bf16 into X rows ----------
        if (lane < 16) {
            uint4 w;
            w.x = cvt2(eaA.x, eaA.y); w.y = cvt2(eaA.z, eaA.w);
            w.z = cvt2(eaB.x, eaB.y); w.w = cvt2(eaB.z, eaB.w);
            *(uint4*)(sXw + bufsel * XTILE + lane * XSTRIDE + 256) = w;
        }
        __syncwarp();

        const u32 lm_base = xbase + (u32)bufsel * XTILE + lm_off;

        // ================= layer 1: 9 k-tiles x 8 n-tiles ==================
        float dacc[8][4];
        #pragma unroll
        for (int j = 0; j < 8; j++)
            #pragma unroll
            for (int q = 0; q < 4; q++) dacc[j][q] = 0.0f;

        #pragma unroll
        for (int tt = 0; tt < NT1; tt++) {
            u32 a0, a1, a2, a3;
            ldsm4(a0, a1, a2, a3, lm_base + tt * 32);
            #pragma unroll
            for (int j = 0; j < 8; j++) {
                uint2 b = sB1f[(tt * 8 + j) * 32 + lane];
                mma16816(dacc[j], a0, a1, a2, a3, b.x, b.y);
            }
        }

        // ===== pack -> bf16x2, packed SiLU -> layer2 A-frags ===============
        u32 a2f[NT2][4];
        #pragma unroll
        for (int j = 0; j < 8; j++) {
            int t2 = j >> 1, hf = (j & 1) * 2;
            a2f[t2][hf + 0] = silu_b2(cvt2(dacc[j][0], dacc[j][1]));
            a2f[t2][hf + 1] = silu_b2(cvt2(dacc[j][2], dacc[j][3]));
        }
        a2f[4][0] = bias_a; a2f[4][1] = bias_a; a2f[4][2] = 0; a2f[4][3] = 0;

        // ================= layer 2: 5 k-tiles x 8 n-tiles ==================
        float eacc[8][4];
        #pragma unroll
        for (int j = 0; j < 8; j++)
            #pragma unroll
            for (int q = 0; q < 4; q++) eacc[j][q] = 0.0f;

        #pragma unroll
        for (int tt = 0; tt < NT2; tt++) {
            #pragma unroll
            for (int j = 0; j < 8; j++) {
                uint2 b = sB2f[(tt * 8 + j) * 32 + lane];
                mma16816(eacc[j], a2f[tt][0], a2f[tt][1], a2f[tt][2], a2f[tt][3],
                         b.x, b.y);
            }
        }

        // ===== packed SiLU(D2) . W3 (bf16x2 dot), quad reduce ==============
        u32 acc_lo = 0, acc_hi = 0;
        #pragma unroll
        for (int j = 0; j < 8; j++) {
            u32 p0 = silu_b2(cvt2(eacc[j][0], eacc[j][1]));   // row lo
            u32 p1 = silu_b2(cvt2(eacc[j][2], eacc[j][3]));   // row hi
            acc_lo = hfma2b(p0, w3p[j], acc_lo);
            acc_hi = hfma2b(p1, w3p[j], acc_hi);
        }
        float s_lo = unpack_sum_b2(acc_lo);
        float s_hi = unpack_sum_b2(acc_hi);
        s_lo += __shfl_xor_sync(FULL, s_lo, 1);
        s_lo += __shfl_xor_sync(FULL, s_lo, 2);
        s_hi += __shfl_xor_sync(FULL, s_hi, 1);
        s_hi += __shfl_xor_sync(FULL, s_hi, 2);

        // ===== epilogue: lane e (0..15) owns edge e ========================
        const int src4 = (lane & 7) * 4;
        float slo_b = __shfl_sync(FULL, s_lo, src4);
        float shi_b = __shfl_sync(FULL, s_hi, src4);
        const float sc = (lane < 8) ? slo_b : shi_b;

        const int rn = __shfl_sync(FULL, t_cur, lane & 15);
        const int cn = __shfl_sync(FULL, t_cur, 16 + (lane & 15));

        if (lane < 16) {
            const float dx = coord[rn * 3 + 0] - coord[cn * 3 + 0];
            const float dy = coord[rn * 3 + 1] - coord[cn * 3 + 1];
            const float dz = coord[rn * 3 + 2] - coord[cn * 3 + 2];
            const float nrm = sqrtf(dx * dx + dy * dy + dz * dz + 1e-8f);
            const float f = sc / ((nrm + 1.0f) * 100.0f);
            atomicAdd(&out[rn * 3 + 0], dx * f);
            atomicAdd(&out[rn * 3 + 1], dy * f);
            atomicAdd(&out[rn * 3 + 2], dz * f);
        }

        t_cur = t_nxt;
        eaA = eaAn; eaB = eaBn;
        g = gn;
        bufsel ^= 1;
        __syncwarp();
    }
}

extern "C" void kernel_launch(void* const* d_in, const int* in_sizes, int n_in,
                              void* d_out, int out_size)
{
    const float* h     = (const float*)d_in[0];
    const float* coord = (const float*)d_in[1];
    const int*   ei    = (const int*)  d_in[2];
    const float* ea    = (const float*)d_in[3];
    const float* W1    = (const float*)d_in[4];
    const float* b1    = (const float*)d_in[5];
    const float* W2    = (const float*)d_in[6];
    const float* b2    = (const float*)d_in[7];
    const float* W3    = (const float*)d_in[8];
    float* out = (float*)d_out;

    const int E  = in_sizes[3] / EIN;     // 1,600,000
    const int h4 = in_sizes[0] / 4;
    const int nmax = (h4 > out_size) ? h4 : out_size;

    prep_kernel<<<(nmax + 255) / 256, 256>>>(h, coord, out, h4, out_size);

    cudaFuncSetAttribute(egnn_mma_kernel,
                         cudaFuncAttributeMaxDynamicSharedMemorySize, SMEM_BYTES);
    egnn_mma_kernel<<<148, NTHREADS, SMEM_BYTES>>>(coord, ei, ea,
                                                   W1, b1, W2, b2, W3, out, E);
}